// round 2
// baseline (speedup 1.0000x reference)
#include <cuda_runtime.h>
#include <cstdint>

// ChainMessagePassing: out[dst] += x[src] over up_index and down_index edges.
// x: [N=100000, D=64] f32; up_index/down_index: [2, E=3200000]
// NOTE: JAX x64 is disabled by default, so the "int64" indices are actually int32.
// row 0 = source, row 1 = target. Output: [N, 64] f32.

#define D_FEAT 64
#define VEC 4
#define CHUNKS (D_FEAT / VEC)   // 16 float4 chunks per feature row
#define CHUNK_SHIFT 4           // log2(CHUNKS)

__global__ void zero_out_kernel(float4* __restrict__ out, int n4) {
    int i = blockIdx.x * blockDim.x + threadIdx.x;
    if (i < n4) out[i] = make_float4(0.f, 0.f, 0.f, 0.f);
}

__global__ void scatter_add_kernel(const float4* __restrict__ x,
                                   const int* __restrict__ up,
                                   const int* __restrict__ down,
                                   float* __restrict__ out,
                                   int num_edges) {
    long long gid = (long long)blockIdx.x * blockDim.x + threadIdx.x;
    long long total = (long long)2 * num_edges * CHUNKS;
    if (gid >= total) return;

    int c = (int)(gid & (CHUNKS - 1));      // which float4 chunk of the 64-dim row
    long long e = gid >> CHUNK_SHIFT;       // global edge id across both edge sets

    const int* idx = up;
    if (e >= num_edges) { idx = down; e -= num_edges; }

    int src = __ldg(&idx[e]);               // row 0: source
    int dst = __ldg(&idx[e + num_edges]);   // row 1: target

    float4 v = __ldg(&x[(long long)src * CHUNKS + c]);

    float* p = out + (long long)dst * D_FEAT + c * VEC;   // 16B-aligned
    asm volatile("red.global.add.v4.f32 [%0], {%1, %2, %3, %4};"
                 :: "l"(p), "f"(v.x), "f"(v.y), "f"(v.z), "f"(v.w)
                 : "memory");
}

extern "C" void kernel_launch(void* const* d_in, const int* in_sizes, int n_in,
                              void* d_out, int out_size) {
    const float4* x    = (const float4*)d_in[0];
    const int*    up   = (const int*)d_in[1];
    const int*    down = (const int*)d_in[2];
    float* out = (float*)d_out;

    // in_sizes[1] = 2 * E elements of the up edge index
    int num_edges = in_sizes[1] / 2;

    // 1) zero the output (poisoned to 0xAA by the harness)
    int n4 = out_size / 4;
    {
        int threads = 256;
        int blocks = (n4 + threads - 1) / threads;
        zero_out_kernel<<<blocks, threads>>>((float4*)out, n4);
    }

    // 2) gather + scatter-add for both edge sets in one launch
    {
        long long total = (long long)2 * num_edges * CHUNKS;   // 102.4M work items
        int threads = 256;
        long long blocks = (total + threads - 1) / threads;
        scatter_add_kernel<<<(unsigned)blocks, threads>>>(x, up, down, out, num_edges);
    }
}

// round 4
// speedup vs baseline: 1.5825x; 1.5825x over previous
#include <cuda_runtime.h>
#include <cstdint>

// ChainMessagePassing: out[dst] += x[src] over up_index and down_index.
// x: [N=100000, D=64] f32; indices are int32 on device (JAX x64 off).
// Strategy: build unordered CSR-by-dst (segment reservation via global cursor,
// no scan), then one register-accumulating gather pass -> zero f32 atomics.

#define MAX_NODES 100000
#define MAX_EDGES 3200000
#define D_FEAT 64

__device__ int g_counts[MAX_NODES];         // degree by dst
__device__ int g_offsets[MAX_NODES];        // segment base (arbitrary order)
__device__ int g_fill[MAX_NODES];           // per-node fill cursor
__device__ int g_cursor;                    // global segment cursor
__device__ int g_edge_src[2 * MAX_EDGES + 4];  // +pad so int4 prefetch is safe

// k0: reset per-replay state
__global__ void reset_kernel(int num_nodes) {
    int i = blockIdx.x * blockDim.x + threadIdx.x;
    if (i < num_nodes) { g_counts[i] = 0; g_fill[i] = 0; }
    if (i == 0) g_cursor = 0;
}

// k1: histogram of destination degrees over both edge sets
__global__ void hist_kernel(const int* __restrict__ up,
                            const int* __restrict__ down,
                            int E) {
    int e = blockIdx.x * blockDim.x + threadIdx.x;
    if (e >= 2 * E) return;
    int dst = (e < E) ? __ldg(&up[e + E]) : __ldg(&down[(e - E) + E]);
    atomicAdd(&g_counts[dst], 1);
}

// k2: reserve a contiguous segment per node (order irrelevant)
__global__ void reserve_kernel(int num_nodes) {
    int n = blockIdx.x * blockDim.x + threadIdx.x;
    if (n >= num_nodes) return;
    g_offsets[n] = atomicAdd(&g_cursor, g_counts[n]);
}

// k3: fill edge source ids into destination segments
__global__ void fill_kernel(const int* __restrict__ up,
                            const int* __restrict__ down,
                            int E) {
    int e = blockIdx.x * blockDim.x + threadIdx.x;
    if (e >= 2 * E) return;
    int src, dst;
    if (e < E) { src = __ldg(&up[e]);        dst = __ldg(&up[e + E]); }
    else       { src = __ldg(&down[e - E]);  dst = __ldg(&down[(e - E) + E]); }
    int pos = g_offsets[dst] + atomicAdd(&g_fill[dst], 1);
    g_edge_src[pos] = src;
}

// k4: warp-per-node gather; each lane accumulates 2 floats of the 64-dim row
__global__ void gather_kernel(const float2* __restrict__ x2,
                              float2* __restrict__ out2,
                              int num_nodes) {
    int warp_id = (blockIdx.x * blockDim.x + threadIdx.x) >> 5;
    if (warp_id >= num_nodes) return;
    int lane = threadIdx.x & 31;

    int deg  = g_counts[warp_id];
    int base = g_offsets[warp_id];

    float2 acc = make_float2(0.f, 0.f);
    int i = 0;
    for (; i + 4 <= deg; i += 4) {
        // one 16B load fetches 4 source ids (segment base not 16B-aligned;
        // read elementwise into int4-shaped regs instead of vector LDG)
        int s0 = __ldg(&g_edge_src[base + i + 0]);
        int s1 = __ldg(&g_edge_src[base + i + 1]);
        int s2 = __ldg(&g_edge_src[base + i + 2]);
        int s3 = __ldg(&g_edge_src[base + i + 3]);
        float2 v0 = __ldg(&x2[(long long)s0 * 32 + lane]);
        float2 v1 = __ldg(&x2[(long long)s1 * 32 + lane]);
        float2 v2 = __ldg(&x2[(long long)s2 * 32 + lane]);
        float2 v3 = __ldg(&x2[(long long)s3 * 32 + lane]);
        acc.x += v0.x + v1.x + v2.x + v3.x;
        acc.y += v0.y + v1.y + v2.y + v3.y;
    }
    for (; i < deg; i++) {
        int s = __ldg(&g_edge_src[base + i]);
        float2 v = __ldg(&x2[(long long)s * 32 + lane]);
        acc.x += v.x;
        acc.y += v.y;
    }
    out2[(long long)warp_id * 32 + lane] = acc;
}

extern "C" void kernel_launch(void* const* d_in, const int* in_sizes, int n_in,
                              void* d_out, int out_size) {
    const float2* x2   = (const float2*)d_in[0];
    const int*    up   = (const int*)d_in[1];
    const int*    down = (const int*)d_in[2];
    float2* out2 = (float2*)d_out;

    int E = in_sizes[1] / 2;              // 3,200,000
    int num_nodes = out_size / D_FEAT;    // 100,000

    const int T = 256;

    reset_kernel<<<(num_nodes + T - 1) / T, T>>>(num_nodes);
    hist_kernel<<<(2 * E + T - 1) / T, T>>>(up, down, E);
    reserve_kernel<<<(num_nodes + T - 1) / T, T>>>(num_nodes);
    fill_kernel<<<(2 * E + T - 1) / T, T>>>(up, down, E);

    long long gather_threads = (long long)num_nodes * 32;
    gather_kernel<<<(unsigned)((gather_threads + T - 1) / T), T>>>(x2, out2, num_nodes);
}

// round 6
// speedup vs baseline: 2.3680x; 1.4964x over previous
#include <cuda_runtime.h>
#include <cstdint>

// ChainMessagePassing: out[dst] += x[src] over up_index and down_index.
// x: [N=100000, D=64] f32; indices are int32 on device (JAX x64 off).
// Strategy: CSR-by-dst built with ONE returning atomic per edge (rank pass),
// hierarchical segment reservation (98 cursor atomics, not 100k), atomic-free
// scatter fill, then register-accumulating gather (zero f32 atomics).

#define MAX_NODES 100000
#define MAX_EDGES 3200000
#define D_FEAT 64
#define SCAN_T 1024

__device__ int g_counts[MAX_NODES];        // degree by dst
__device__ int g_offsets[MAX_NODES];       // segment base (arbitrary order)
__device__ int g_cursor;                   // global segment cursor
__device__ int g_rank[2 * MAX_EDGES];      // edge's slot within its dst segment
__device__ int g_edge_src[2 * MAX_EDGES];  // CSR payload: source node ids

// k0: reset per-replay state
__global__ void reset_kernel(int num_nodes) {
    int i = blockIdx.x * blockDim.x + threadIdx.x;
    if (i < num_nodes) g_counts[i] = 0;
    if (i == 0) g_cursor = 0;
}

// k1: one returning atomic per edge -> degree histogram + per-edge rank
__global__ void rank_kernel(const int* __restrict__ up,
                            const int* __restrict__ down,
                            int E) {
    int e = blockIdx.x * blockDim.x + threadIdx.x;
    if (e >= 2 * E) return;
    int dst = (e < E) ? __ldg(&up[e + E]) : __ldg(&down[(e - E) + E]);
    g_rank[e] = atomicAdd(&g_counts[dst], 1);   // coalesced write of rank
}

// k2: hierarchical reservation: intra-block scan + one cursor atomic per block
__global__ void reserve_kernel(int num_nodes) {
    __shared__ int s[SCAN_T];
    __shared__ int s_base;
    int tid = threadIdx.x;
    int i = blockIdx.x * SCAN_T + tid;
    int c = (i < num_nodes) ? g_counts[i] : 0;
    s[tid] = c;
    __syncthreads();
    // Hillis-Steele inclusive scan over SCAN_T elements
    #pragma unroll
    for (int off = 1; off < SCAN_T; off <<= 1) {
        int v = (tid >= off) ? s[tid - off] : 0;
        __syncthreads();
        s[tid] += v;
        __syncthreads();
    }
    if (tid == SCAN_T - 1) s_base = atomicAdd(&g_cursor, s[SCAN_T - 1]);
    __syncthreads();
    if (i < num_nodes) g_offsets[i] = s_base + s[tid] - c;  // exclusive
}

// k3: atomic-free scatter fill using precomputed ranks
__global__ void fill_kernel(const int* __restrict__ up,
                            const int* __restrict__ down,
                            int E) {
    int e = blockIdx.x * blockDim.x + threadIdx.x;
    if (e >= 2 * E) return;
    int src, dst;
    if (e < E) { src = __ldg(&up[e]);        dst = __ldg(&up[e + E]); }
    else       { src = __ldg(&down[e - E]);  dst = __ldg(&down[(e - E) + E]); }
    g_edge_src[g_offsets[dst] + g_rank[e]] = src;
}

// k4: warp-per-node gather; each lane accumulates 2 floats of the 64-dim row
__global__ void gather_kernel(const float2* __restrict__ x2,
                              float2* __restrict__ out2,
                              int num_nodes) {
    int warp_id = (blockIdx.x * blockDim.x + threadIdx.x) >> 5;
    if (warp_id >= num_nodes) return;
    int lane = threadIdx.x & 31;

    int deg  = g_counts[warp_id];
    int base = g_offsets[warp_id];

    float2 acc = make_float2(0.f, 0.f);
    int i = 0;
    for (; i + 8 <= deg; i += 8) {
        int s[8];
        #pragma unroll
        for (int k = 0; k < 8; k++) s[k] = __ldg(&g_edge_src[base + i + k]);
        float2 v[8];
        #pragma unroll
        for (int k = 0; k < 8; k++) v[k] = __ldg(&x2[(long long)s[k] * 32 + lane]);
        #pragma unroll
        for (int k = 0; k < 8; k++) { acc.x += v[k].x; acc.y += v[k].y; }
    }
    for (; i < deg; i++) {
        int s = __ldg(&g_edge_src[base + i]);
        float2 v = __ldg(&x2[(long long)s * 32 + lane]);
        acc.x += v.x;
        acc.y += v.y;
    }
    out2[(long long)warp_id * 32 + lane] = acc;
}

extern "C" void kernel_launch(void* const* d_in, const int* in_sizes, int n_in,
                              void* d_out, int out_size) {
    const float2* x2   = (const float2*)d_in[0];
    const int*    up   = (const int*)d_in[1];
    const int*    down = (const int*)d_in[2];
    float2* out2 = (float2*)d_out;

    int E = in_sizes[1] / 2;              // 3,200,000
    int num_nodes = out_size / D_FEAT;    // 100,000

    const int T = 256;

    reset_kernel<<<(num_nodes + T - 1) / T, T>>>(num_nodes);
    rank_kernel<<<(2 * E + T - 1) / T, T>>>(up, down, E);
    reserve_kernel<<<(num_nodes + SCAN_T - 1) / SCAN_T, SCAN_T>>>(num_nodes);
    fill_kernel<<<(2 * E + T - 1) / T, T>>>(up, down, E);

    long long gather_threads = (long long)num_nodes * 32;
    gather_kernel<<<(unsigned)((gather_threads + T - 1) / T), T>>>(x2, out2, num_nodes);
}